// round 10
// baseline (speedup 1.0000x reference)
#include <cuda_runtime.h>

#define AA 500000
#define CC 91
#define NCLS 90
#define KK 100
#define DD 200
#define POOLCAP 16384
#define FCAP 2048
#define HBINS 80
#define HPAD 81
#define HBASE 1968   /* 123<<4 : bins cover p in [2^-4, 2) with 4 mantissa bits */
#define GATE 0.0625f
#define SBINS 1024
#define SBASE 15360
#define SCORE_T 0.01f
#define NMS_T 0.45f
#define NEG_INF -1e30f
#define BBOX_CLIP 4.135166556742356f
#define IMG 512.0f

// ---------------- scratch (static device globals; no allocation) ----------------
__device__ int   g_hist[NCLS * HBINS];
__device__ float g_thrC[NCLS];          // score-space threshold (0 => keep all)
__device__ int   g_cnt[NCLS];
__device__ unsigned long long g_pool[NCLS * POOLCAP];
__device__ float g_vals[NCLS * KK];
__device__ int   g_anchor[NCLS * KK];
__device__ float g_boxes[NCLS * KK * 4];
__device__ int   g_keptK[NCLS * KK];
__device__ int   g_kc[NCLS];
__device__ int   g_selA[DD];
__device__ int   g_numKept;

__device__ __forceinline__ int hbin(float p) {
    int b = (int)(__float_as_uint(p) >> 19) - HBASE;
    return b < 0 ? 0 : (b > HBINS - 1 ? HBINS - 1 : b);
}

// ---------------- K0: zero per-launch state (graph replays!) --------------------
__global__ void k_zero() {
    int t = blockIdx.x * blockDim.x + threadIdx.x;
    int stride = gridDim.x * blockDim.x;
    for (int i = t; i < NCLS * HBINS; i += stride) g_hist[i] = 0;
    if (t < NCLS) g_cnt[t] = 0;
}

// ---------------- K1: fused softmax + histogram + candidate pooling -------------
__device__ __forceinline__ void push(float p, int r, int a, unsigned int* sh) {
    if (p > GATE) {
        atomicAdd(&sh[r * HPAD + hbin(p)], 1u);
        int pos = atomicAdd(&g_cnt[r], 1);
        if (pos < POOLCAP)
            g_pool[r * POOLCAP + pos] =
                ((unsigned long long)__float_as_uint(p) << 32) | (unsigned)(~(unsigned)a);
    }
}

__global__ void k_stats(const float* __restrict__ logits) {
    __shared__ unsigned int sh[NCLS * HPAD];   // stride 81 (odd) -> conflict-free
    for (int i = threadIdx.x; i < NCLS * HPAD; i += blockDim.x) sh[i] = 0u;
    __syncthreads();
    int lane = threadIdx.x & 31;
    int gw = (blockIdx.x * blockDim.x + threadIdx.x) >> 5;
    int nw = (gridDim.x * blockDim.x) >> 5;
    for (int a = gw * 2; a < AA; a += nw * 2) {       // AA even -> a+1 always valid
        const float* rA = logits + (size_t)a * CC;
        const float* rB = rA + CC;
        float zA0 = rA[lane], zA1 = rA[lane + 32];
        float zB0 = rB[lane], zB1 = rB[lane + 32];
        float eA2 = 0.f, eB2 = 0.f;
        if (lane < 27) { eA2 = __expf(rA[lane + 64]); eB2 = __expf(rB[lane + 64]); }
        float eA0 = __expf(zA0), eA1 = __expf(zA1);
        float eB0 = __expf(zB0), eB1 = __expf(zB1);
        float sA = eA0 + eA1 + eA2;
        float sB = eB0 + eB1 + eB2;
#pragma unroll
        for (int o = 16; o; o >>= 1) {
            sA += __shfl_xor_sync(0xffffffffu, sA, o);
            sB += __shfl_xor_sync(0xffffffffu, sB, o);
        }
        float iA = __frcp_rn(sA), iB = __frcp_rn(sB);
        if (lane > 0) {
            push(eA0 * iA, lane - 1, a, sh);
            push(eB0 * iB, lane - 1, a + 1, sh);
        }
        push(eA1 * iA, lane + 31, a, sh);
        push(eB1 * iB, lane + 31, a + 1, sh);
        if (lane < 27) {
            push(eA2 * iA, lane + 63, a, sh);
            push(eB2 * iB, lane + 63, a + 1, sh);
        }
    }
    __syncthreads();
    for (int i = threadIdx.x; i < NCLS * HPAD; i += blockDim.x) {
        int b = i % HPAD;
        if (b < HBINS) {
            unsigned v = sh[i];
            if (v) atomicAdd(&g_hist[(i / HPAD) * HBINS + b], (int)v);
        }
    }
}

// ---------------- K2: per-class cutoff -> score-space threshold -----------------
__global__ void k_cut() {
    int c = blockIdx.x;
    __shared__ int h[HBINS];
    if (threadIdx.x < HBINS) h[threadIdx.x] = g_hist[c * HBINS + threadIdx.x];
    __syncthreads();
    if (threadIdx.x == 0) {
        int cum = 0, cut = 0;
        for (int b = HBINS - 1; b >= 0; --b) {
            cum += h[b];
            if (cum >= KK) { cut = b; break; }
        }
        g_thrC[c] = (cut <= 0) ? 0.f
                              : __uint_as_float((unsigned)(cut - 1 + HBASE) << 19);
    }
}

// ---------------- K3: filter pool + topK sort + decode + NMS (fused) ------------
__global__ void k_topcls(const float* __restrict__ breg, const float* __restrict__ anchors) {
    __shared__ unsigned long long sk[FCAP];   // 16 KB
    __shared__ float sbx[KK * 4];
    __shared__ unsigned adj[KK * 4];
    __shared__ int sCnt;
    int c = blockIdx.x, tid = threadIdx.x;
    unsigned thrBits = __float_as_uint(g_thrC[c]);
    int n = g_cnt[c]; if (n > POOLCAP) n = POOLCAP;
    if (tid == 0) sCnt = 0;
    __syncthreads();
    for (int i = tid; i < n; i += 256) {
        unsigned long long key = g_pool[c * POOLCAP + i];
        if ((unsigned)(key >> 32) > thrBits) {     // positive floats: uint cmp == float cmp
            int pos = atomicAdd(&sCnt, 1);
            if (pos < FCAP) sk[pos] = key;
        }
    }
    __syncthreads();
    int m = sCnt; if (m > FCAP) m = FCAP;
    int npad = 2; while (npad < m) npad <<= 1;
    for (int i = tid; i < npad; i += 256) if (i >= m) sk[i] = 0ull;
    __syncthreads();
    for (int size = 2; size <= npad; size <<= 1) {
        for (int stride = size >> 1; stride > 0; stride >>= 1) {
            for (int t = tid; t < (npad >> 1); t += 256) {
                int i = ((t & ~(stride - 1)) << 1) | (t & (stride - 1));
                int j = i + stride;
                bool dsc = ((i & size) == 0);
                unsigned long long x = sk[i], y = sk[j];
                if (dsc == (x < y)) { sk[i] = y; sk[j] = x; }
            }
            __syncthreads();
        }
    }
    int nv = m < KK ? m : KK;
    // decode + clip top KK
    for (int k = tid; k < KK; k += 256) {
        float val; int a;
        if (k < nv) {
            unsigned long long key = sk[k];
            val = __uint_as_float((unsigned)(key >> 32));
            a = (int)(~(unsigned)key);
        } else { val = NEG_INF; a = 0; }
        g_vals[c * KK + k] = val;
        g_anchor[c * KK + k] = a;
        float b0 = 0.f, b1 = 0.f, b2 = 0.f, b3 = 0.f;
        if (k < nv) {
            float ax1 = anchors[a * 4 + 0], ay1 = anchors[a * 4 + 1];
            float ax2 = anchors[a * 4 + 2], ay2 = anchors[a * 4 + 3];
            float wa = ax2 - ax1, ha = ay2 - ay1;
            float cxa = ax1 + 0.5f * wa, cya = ay1 + 0.5f * ha;
            float r0 = breg[a * 4 + 0], r1 = breg[a * 4 + 1];
            float r2 = breg[a * 4 + 2], r3 = breg[a * 4 + 3];
            float dx = r0 / 10.0f, dy = r1 / 10.0f;
            float dw = fminf(r2 / 5.0f, BBOX_CLIP), dh = fminf(r3 / 5.0f, BBOX_CLIP);
            float cx = dx * wa + cxa, cy = dy * ha + cya;
            float w = expf(dw) * wa, h = expf(dh) * ha;
            b0 = cx - 0.5f * w; b1 = cy - 0.5f * h;
            b2 = cx + 0.5f * w; b3 = cy + 0.5f * h;
            b0 = fminf(fmaxf(b0, 0.f), IMG); b1 = fminf(fmaxf(b1, 0.f), IMG);
            b2 = fminf(fmaxf(b2, 0.f), IMG); b3 = fminf(fmaxf(b3, 0.f), IMG);
        }
        g_boxes[(c * KK + k) * 4 + 0] = b0;  sbx[k * 4 + 0] = b0;
        g_boxes[(c * KK + k) * 4 + 1] = b1;  sbx[k * 4 + 1] = b1;
        g_boxes[(c * KK + k) * 4 + 2] = b2;  sbx[k * 4 + 2] = b2;
        g_boxes[(c * KK + k) * 4 + 3] = b3;  sbx[k * 4 + 3] = b3;
    }
    __syncthreads();
    // IoU adjacency bitmap (within-class: label offset cancels exactly)
    for (int idx = tid; idx < KK * 4; idx += 256) {
        int i = idx >> 2, w = idx & 3;
        unsigned mask = 0u;
        if (i < nv) {
            float ix1 = sbx[i * 4 + 0], iy1 = sbx[i * 4 + 1];
            float ix2 = sbx[i * 4 + 2], iy2 = sbx[i * 4 + 3];
            float areai = (ix2 - ix1) * (iy2 - iy1);
            int j0 = w * 32;
            int jend = nv - j0; if (jend > 32) jend = 32;
            for (int b = 0; b < jend; b++) {
                int j = j0 + b;
                float jx1 = sbx[j * 4 + 0], jy1 = sbx[j * 4 + 1];
                float jx2 = sbx[j * 4 + 2], jy2 = sbx[j * 4 + 3];
                float ltx = fmaxf(ix1, jx1), lty = fmaxf(iy1, jy1);
                float rbx = fminf(ix2, jx2), rby = fminf(iy2, jy2);
                float w2 = fmaxf(rbx - ltx, 0.f), h2 = fmaxf(rby - lty, 0.f);
                float inter = w2 * h2;
                float areaj = (jx2 - jx1) * (jy2 - jy1);
                float iou = inter / fmaxf(areai + areaj - inter, 1e-9f);
                if (iou > NMS_T) mask |= (1u << b);
            }
        }
        adj[idx] = mask;
    }
    __syncthreads();
    if (tid == 0) {
        unsigned supp[4];
#pragma unroll
        for (int w = 0; w < 4; w++) {
            int lo = w * 32;
            if (nv >= lo + 32) supp[w] = 0u;
            else if (nv <= lo) supp[w] = 0xFFFFFFFFu;
            else supp[w] = ~((1u << (nv - lo)) - 1u);
        }
        int kc = 0;
        for (int i = 0; i < KK; i++) {
            if (!((supp[i >> 5] >> (i & 31)) & 1u)) {
                g_keptK[c * KK + kc++] = i;
                supp[0] |= adj[i * 4 + 0]; supp[1] |= adj[i * 4 + 1];
                supp[2] |= adj[i * 4 + 2]; supp[3] |= adj[i * 4 + 3];
            }
        }
        g_kc[c] = kc;
    }
}

// ---------------- K4: global top-D select + scalar outputs ----------------------
__global__ void k_final(float* __restrict__ out) {
    __shared__ int sPref[NCLS + 1];
    __shared__ int sHist[SBINS];
    __shared__ unsigned long long sKeys[1024];
    __shared__ int sCnt, sB, sNum;
    int tid = threadIdx.x;  // 256
    for (int i = tid; i < SBINS; i += 256) sHist[i] = 0;
    if (tid < NCLS) sPref[tid + 1] = g_kc[tid];
    if (tid == 0) { sPref[0] = 0; sCnt = 0; }
    __syncthreads();
    if (tid == 0)
        for (int c = 1; c <= NCLS; c++) sPref[c] += sPref[c - 1];
    __syncthreads();
    int tot = sPref[NCLS];
    for (int g = tid; g < tot; g += 256) {
        int lo = 0, hi = NCLS;
        while (hi - lo > 1) { int mid = (lo + hi) >> 1; if (sPref[mid] <= g) lo = mid; else hi = mid; }
        int c = lo, j = g - sPref[c];
        int k = g_keptK[c * KK + j];
        unsigned v = __float_as_uint(g_vals[c * KK + k]);
        int b = (int)(v >> 16) - SBASE;
        b = b < 0 ? 0 : (b > SBINS - 1 ? SBINS - 1 : b);
        atomicAdd(&sHist[b], 1);
    }
    __syncthreads();
    int r = tot < DD ? tot : DD;
    if (tid == 0) {
        int cum = 0, b = 0;
        for (int i = SBINS - 1; i >= 0; --i) { cum += sHist[i]; if (cum >= r) { b = i; break; } }
        sB = (r > 0) ? b : SBINS;
        sNum = r;
        g_numKept = r;
    }
    __syncthreads();
    int bstar = sB;
    for (int g = tid; g < tot; g += 256) {
        int lo = 0, hi = NCLS;
        while (hi - lo > 1) { int mid = (lo + hi) >> 1; if (sPref[mid] <= g) lo = mid; else hi = mid; }
        int c = lo, j = g - sPref[c];
        int k = g_keptK[c * KK + j];
        int ci = c * KK + k;
        unsigned v = __float_as_uint(g_vals[ci]);
        int b = (int)(v >> 16) - SBASE;
        b = b < 0 ? 0 : (b > SBINS - 1 ? SBINS - 1 : b);
        if (b >= bstar) {
            int pos = atomicAdd(&sCnt, 1);
            if (pos < 1024)
                sKeys[pos] = ((unsigned long long)v << 32) |
                             (unsigned long long)(0xFFFFFFFFu - (unsigned)ci);
        }
    }
    __syncthreads();
    int cnt = sCnt; if (cnt > 1024) cnt = 1024;
    for (int i = tid; i < 1024; i += 256) if (i >= cnt) sKeys[i] = 0ull;
    __syncthreads();
    for (int size = 2; size <= 1024; size <<= 1) {
        for (int stride = size >> 1; stride > 0; stride >>= 1) {
            for (int t = tid; t < 512; t += 256) {
                int i = ((t & ~(stride - 1)) << 1) | (t & (stride - 1));
                int j = i + stride;
                bool dsc = ((i & size) == 0);
                unsigned long long x = sKeys[i], y = sKeys[j];
                if (dsc == (x < y)) { sKeys[i] = y; sKeys[j] = x; }
            }
            __syncthreads();
        }
    }
    int num = sNum;
    for (int t = tid; t < DD; t += 256) {
        if (t < num) {
            unsigned long long key = sKeys[t];
            int ci = (int)(0xFFFFFFFFu - (unsigned)key);
            int c = ci / KK;
            g_selA[t] = g_anchor[ci];
            out[t * 4 + 0] = g_boxes[ci * 4 + 1];
            out[t * 4 + 1] = g_boxes[ci * 4 + 0];
            out[t * 4 + 2] = g_boxes[ci * 4 + 3];
            out[t * 4 + 3] = g_boxes[ci * 4 + 2];
            out[DD * 4 + t] = __uint_as_float((unsigned)(key >> 32));
            out[DD * 5 + t] = (float)(c + 1);
        } else {
            g_selA[t] = -1;
            out[t * 4 + 0] = 0.f; out[t * 4 + 1] = 0.f;
            out[t * 4 + 2] = 0.f; out[t * 4 + 3] = 0.f;
            out[DD * 4 + t] = 0.f;
            out[DD * 5 + t] = 0.f;
        }
    }
}

// ---------------- K5: logit gather (one block per detection) --------------------
__global__ void k_gather(float* __restrict__ out, const float* __restrict__ logits) {
    int t = blockIdx.x, tid = threadIdx.x;
    int a = g_selA[t];
    if (a >= 0) {
        const float* row = logits + (size_t)a * CC;
        for (int j = tid; j < CC; j += blockDim.x)
            out[DD * 6 + t * CC + j] = row[j];
    } else {
        for (int j = tid; j < CC; j += blockDim.x)
            out[DD * 6 + t * CC + j] = 0.f;
    }
}

extern "C" void kernel_launch(void* const* d_in, const int* in_sizes, int n_in,
                              void* d_out, int out_size) {
    const float* logits = (const float*)d_in[0];
    const float* breg = (const float*)d_in[1];
    const float* anchors = (const float*)d_in[2];
    float* out = (float*)d_out;

    k_zero<<<32, 256>>>();
    k_stats<<<740, 256>>>(logits);
    k_cut<<<NCLS, 96>>>();
    k_topcls<<<NCLS, 256>>>(breg, anchors);
    k_final<<<1, 256>>>(out);
    k_gather<<<DD, 128>>>(out, logits);
}

// round 11
// speedup vs baseline: 2.1052x; 2.1052x over previous
#include <cuda_runtime.h>

#define AA 500000
#define CC 91
#define NCLS 90
#define KK 100
#define DD 200
#define POOLCAP 16384
#define SCAP 1536
#define FCAP 2048
#define HBINS 80
#define HPAD 81
#define HBASE 1968   /* 123<<4 : bins cover p in [2^-4, 2) with 4 mantissa bits */
#define GATE 0.0625f
#define SBINS 1024
#define SBASE 15360
#define SCORE_T 0.01f
#define NMS_T 0.45f
#define NEG_INF -1e30f
#define BBOX_CLIP 4.135166556742356f
#define IMG 512.0f

// ---------------- scratch (static device globals; no allocation) ----------------
__device__ int   g_hist[NCLS * HBINS];
__device__ unsigned g_thrU[NCLS];       // exact score-bits threshold (0 => keep all)
__device__ int   g_cnt[NCLS];
__device__ unsigned long long g_pool[NCLS * POOLCAP];
__device__ float g_vals[NCLS * KK];
__device__ int   g_anchor[NCLS * KK];
__device__ float g_boxes[NCLS * KK * 4];
__device__ int   g_keptK[NCLS * KK];
__device__ int   g_kc[NCLS];
__device__ int   g_selA[DD];

__device__ __forceinline__ int hbin(float p) {
    int b = (int)(__float_as_uint(p) >> 19) - HBASE;
    return b < 0 ? 0 : (b > HBINS - 1 ? HBINS - 1 : b);
}

// ---------------- K0: zero per-launch state (graph replays!) --------------------
__global__ void k_zero() {
    int t = blockIdx.x * blockDim.x + threadIdx.x;
    int stride = gridDim.x * blockDim.x;
    for (int i = t; i < NCLS * HBINS; i += stride) g_hist[i] = 0;
    if (t < NCLS) g_cnt[t] = 0;
}

// ---------------- K1: fused softmax + histogram + block-staged pooling ----------
struct Stage {
    unsigned long long key[SCAP];
    unsigned char cls[SCAP];
    int top;
    int ccnt[NCLS];
    int base[NCLS];
    int cur[NCLS];
};

__device__ __forceinline__ void push(float p, int r, int a,
                                     unsigned int* sh, Stage* st) {
    if (p > GATE) {
        atomicAdd(&sh[r * HPAD + hbin(p)], 1u);
        unsigned long long key =
            ((unsigned long long)__float_as_uint(p) << 32) | (unsigned)(~(unsigned)a);
        int pos = atomicAdd(&st->top, 1);
        if (pos < SCAP) {
            st->key[pos] = key;
            st->cls[pos] = (unsigned char)r;
            atomicAdd(&st->ccnt[r], 1);
        } else {                                   // rare overflow: direct global
            int gp = atomicAdd(&g_cnt[r], 1);
            if (gp < POOLCAP) g_pool[r * POOLCAP + gp] = key;
        }
    }
}

__global__ void k_stats(const float* __restrict__ logits) {
    __shared__ unsigned int sh[NCLS * HPAD];   // 29160 B, stride 81 -> conflict-free
    __shared__ Stage st;                        // ~14.9 KB
    for (int i = threadIdx.x; i < NCLS * HPAD; i += blockDim.x) sh[i] = 0u;
    for (int i = threadIdx.x; i < NCLS; i += blockDim.x) { st.ccnt[i] = 0; st.cur[i] = 0; }
    if (threadIdx.x == 0) st.top = 0;
    __syncthreads();
    int lane = threadIdx.x & 31;
    int gw = (blockIdx.x * blockDim.x + threadIdx.x) >> 5;
    int nw = (gridDim.x * blockDim.x) >> 5;
    for (int a = gw * 2; a < AA; a += nw * 2) {       // AA even -> a+1 valid
        const float* rA = logits + (size_t)a * CC;
        const float* rB = rA + CC;
        float zA0 = rA[lane], zA1 = rA[lane + 32];
        float zB0 = rB[lane], zB1 = rB[lane + 32];
        float eA2 = 0.f, eB2 = 0.f;
        if (lane < 27) { eA2 = __expf(rA[lane + 64]); eB2 = __expf(rB[lane + 64]); }
        float eA0 = __expf(zA0), eA1 = __expf(zA1);
        float eB0 = __expf(zB0), eB1 = __expf(zB1);
        float sA = eA0 + eA1 + eA2;
        float sB = eB0 + eB1 + eB2;
#pragma unroll
        for (int o = 16; o; o >>= 1) {
            sA += __shfl_xor_sync(0xffffffffu, sA, o);
            sB += __shfl_xor_sync(0xffffffffu, sB, o);
        }
        float iA = __frcp_rn(sA), iB = __frcp_rn(sB);
        if (lane > 0) {
            push(eA0 * iA, lane - 1, a, sh, &st);
            push(eB0 * iB, lane - 1, a + 1, sh, &st);
        }
        push(eA1 * iA, lane + 31, a, sh, &st);
        push(eB1 * iB, lane + 31, a + 1, sh, &st);
        if (lane < 27) {
            push(eA2 * iA, lane + 63, a, sh, &st);
            push(eB2 * iB, lane + 63, a + 1, sh, &st);
        }
    }
    __syncthreads();
    // bulk-reserve pool slots: one global atomic per class per block
    if (threadIdx.x < NCLS) {
        int c = threadIdx.x, n = st.ccnt[c];
        st.base[c] = n ? atomicAdd(&g_cnt[c], n) : 0;
    }
    __syncthreads();
    int top = st.top < SCAP ? st.top : SCAP;
    for (int i = threadIdx.x; i < top; i += blockDim.x) {
        int c = st.cls[i];
        int rk = atomicAdd(&st.cur[c], 1);
        int gp = st.base[c] + rk;
        if (gp < POOLCAP) g_pool[c * POOLCAP + gp] = st.key[i];
    }
    // flush histogram
    for (int i = threadIdx.x; i < NCLS * HPAD; i += blockDim.x) {
        int b = i % HPAD;
        if (b < HBINS) {
            unsigned v = sh[i];
            if (v) atomicAdd(&g_hist[(i / HPAD) * HBINS + b], (int)v);
        }
    }
}

// ---------------- K2: per-class cutoff -> exact bits threshold ------------------
__global__ void k_cut() {
    int c = blockIdx.x;
    __shared__ int h[HBINS];
    if (threadIdx.x < HBINS) h[threadIdx.x] = g_hist[c * HBINS + threadIdx.x];
    __syncthreads();
    if (threadIdx.x == 0) {
        int cum = 0, cut = 0;
        for (int b = HBINS - 1; b >= 0; --b) {
            cum += h[b];
            if (cum >= KK) { cut = b; break; }
        }
        g_thrU[c] = (cut <= 0) ? 0u : ((unsigned)(cut + HBASE) << 19);
    }
}

// ---------------- K3: filter pool + topK sort + decode + NMS (fused) ------------
__global__ void k_topcls(const float* __restrict__ breg, const float* __restrict__ anchors) {
    __shared__ unsigned long long sk[FCAP];   // 16 KB
    __shared__ float sbx[KK * 4];
    __shared__ unsigned adj[KK * 4];
    __shared__ int sCnt;
    int c = blockIdx.x, tid = threadIdx.x;
    unsigned thrBits = g_thrU[c];
    int n = g_cnt[c]; if (n > POOLCAP) n = POOLCAP;
    if (tid == 0) sCnt = 0;
    __syncthreads();
    for (int i = tid; i < n; i += 256) {
        unsigned long long key = g_pool[c * POOLCAP + i];
        if ((unsigned)(key >> 32) >= thrBits) {   // exact same bits as histogram
            int pos = atomicAdd(&sCnt, 1);
            if (pos < FCAP) sk[pos] = key;
        }
    }
    __syncthreads();
    int m = sCnt; if (m > FCAP) m = FCAP;
    int npad = 2; while (npad < m) npad <<= 1;
    for (int i = tid; i < npad; i += 256) if (i >= m) sk[i] = 0ull;
    __syncthreads();
    for (int size = 2; size <= npad; size <<= 1) {
        for (int stride = size >> 1; stride > 0; stride >>= 1) {
            for (int t = tid; t < (npad >> 1); t += 256) {
                int i = ((t & ~(stride - 1)) << 1) | (t & (stride - 1));
                int j = i + stride;
                bool dsc = ((i & size) == 0);
                unsigned long long x = sk[i], y = sk[j];
                if (dsc == (x < y)) { sk[i] = y; sk[j] = x; }
            }
            __syncthreads();
        }
    }
    int nv = m < KK ? m : KK;
    for (int k = tid; k < KK; k += 256) {
        float val; int a;
        if (k < nv) {
            unsigned long long key = sk[k];
            val = __uint_as_float((unsigned)(key >> 32));
            a = (int)(~(unsigned)key);
        } else { val = NEG_INF; a = 0; }
        g_vals[c * KK + k] = val;
        g_anchor[c * KK + k] = a;
        float b0 = 0.f, b1 = 0.f, b2 = 0.f, b3 = 0.f;
        if (k < nv) {
            float ax1 = anchors[a * 4 + 0], ay1 = anchors[a * 4 + 1];
            float ax2 = anchors[a * 4 + 2], ay2 = anchors[a * 4 + 3];
            float wa = ax2 - ax1, ha = ay2 - ay1;
            float cxa = ax1 + 0.5f * wa, cya = ay1 + 0.5f * ha;
            float r0 = breg[a * 4 + 0], r1 = breg[a * 4 + 1];
            float r2 = breg[a * 4 + 2], r3 = breg[a * 4 + 3];
            float dx = r0 / 10.0f, dy = r1 / 10.0f;
            float dw = fminf(r2 / 5.0f, BBOX_CLIP), dh = fminf(r3 / 5.0f, BBOX_CLIP);
            float cx = dx * wa + cxa, cy = dy * ha + cya;
            float w = expf(dw) * wa, h = expf(dh) * ha;
            b0 = cx - 0.5f * w; b1 = cy - 0.5f * h;
            b2 = cx + 0.5f * w; b3 = cy + 0.5f * h;
            b0 = fminf(fmaxf(b0, 0.f), IMG); b1 = fminf(fmaxf(b1, 0.f), IMG);
            b2 = fminf(fmaxf(b2, 0.f), IMG); b3 = fminf(fmaxf(b3, 0.f), IMG);
        }
        g_boxes[(c * KK + k) * 4 + 0] = b0;  sbx[k * 4 + 0] = b0;
        g_boxes[(c * KK + k) * 4 + 1] = b1;  sbx[k * 4 + 1] = b1;
        g_boxes[(c * KK + k) * 4 + 2] = b2;  sbx[k * 4 + 2] = b2;
        g_boxes[(c * KK + k) * 4 + 3] = b3;  sbx[k * 4 + 3] = b3;
    }
    __syncthreads();
    // IoU adjacency bitmap (within-class: label offset cancels exactly)
    for (int idx = tid; idx < KK * 4; idx += 256) {
        int i = idx >> 2, w = idx & 3;
        unsigned mask = 0u;
        if (i < nv) {
            float ix1 = sbx[i * 4 + 0], iy1 = sbx[i * 4 + 1];
            float ix2 = sbx[i * 4 + 2], iy2 = sbx[i * 4 + 3];
            float areai = (ix2 - ix1) * (iy2 - iy1);
            int j0 = w * 32;
            int jend = nv - j0; if (jend > 32) jend = 32;
            for (int b = 0; b < jend; b++) {
                int j = j0 + b;
                float jx1 = sbx[j * 4 + 0], jy1 = sbx[j * 4 + 1];
                float jx2 = sbx[j * 4 + 2], jy2 = sbx[j * 4 + 3];
                float ltx = fmaxf(ix1, jx1), lty = fmaxf(iy1, jy1);
                float rbx = fminf(ix2, jx2), rby = fminf(iy2, jy2);
                float w2 = fmaxf(rbx - ltx, 0.f), h2 = fmaxf(rby - lty, 0.f);
                float inter = w2 * h2;
                float areaj = (jx2 - jx1) * (jy2 - jy1);
                float iou = inter / fmaxf(areai + areaj - inter, 1e-9f);
                if (iou > NMS_T) mask |= (1u << b);
            }
        }
        adj[idx] = mask;
    }
    __syncthreads();
    if (tid == 0) {
        unsigned supp[4];
#pragma unroll
        for (int w = 0; w < 4; w++) {
            int lo = w * 32;
            if (nv >= lo + 32) supp[w] = 0u;
            else if (nv <= lo) supp[w] = 0xFFFFFFFFu;
            else supp[w] = ~((1u << (nv - lo)) - 1u);
        }
        int kc = 0;
        for (int i = 0; i < KK; i++) {
            if (!((supp[i >> 5] >> (i & 31)) & 1u)) {
                g_keptK[c * KK + kc++] = i;
                supp[0] |= adj[i * 4 + 0]; supp[1] |= adj[i * 4 + 1];
                supp[2] |= adj[i * 4 + 2]; supp[3] |= adj[i * 4 + 3];
            }
        }
        g_kc[c] = kc;
    }
}

// ---------------- K4: global top-D select + scalar outputs ----------------------
__global__ void k_final(float* __restrict__ out) {
    __shared__ int sPref[NCLS + 1];
    __shared__ int sHist[SBINS];
    __shared__ unsigned long long sKeys[1024];
    __shared__ int sCnt, sB, sNum;
    int tid = threadIdx.x;  // 256
    for (int i = tid; i < SBINS; i += 256) sHist[i] = 0;
    if (tid < NCLS) sPref[tid + 1] = g_kc[tid];
    if (tid == 0) { sPref[0] = 0; sCnt = 0; }
    __syncthreads();
    if (tid == 0)
        for (int c = 1; c <= NCLS; c++) sPref[c] += sPref[c - 1];
    __syncthreads();
    int tot = sPref[NCLS];
    for (int g = tid; g < tot; g += 256) {
        int lo = 0, hi = NCLS;
        while (hi - lo > 1) { int mid = (lo + hi) >> 1; if (sPref[mid] <= g) lo = mid; else hi = mid; }
        int c = lo, j = g - sPref[c];
        int k = g_keptK[c * KK + j];
        unsigned v = __float_as_uint(g_vals[c * KK + k]);
        int b = (int)(v >> 16) - SBASE;
        b = b < 0 ? 0 : (b > SBINS - 1 ? SBINS - 1 : b);
        atomicAdd(&sHist[b], 1);
    }
    __syncthreads();
    int r = tot < DD ? tot : DD;
    if (tid == 0) {
        int cum = 0, b = 0;
        for (int i = SBINS - 1; i >= 0; --i) { cum += sHist[i]; if (cum >= r) { b = i; break; } }
        sB = (r > 0) ? b : SBINS;
        sNum = r;
    }
    __syncthreads();
    int bstar = sB;
    for (int g = tid; g < tot; g += 256) {
        int lo = 0, hi = NCLS;
        while (hi - lo > 1) { int mid = (lo + hi) >> 1; if (sPref[mid] <= g) lo = mid; else hi = mid; }
        int c = lo, j = g - sPref[c];
        int k = g_keptK[c * KK + j];
        int ci = c * KK + k;
        unsigned v = __float_as_uint(g_vals[ci]);
        int b = (int)(v >> 16) - SBASE;
        b = b < 0 ? 0 : (b > SBINS - 1 ? SBINS - 1 : b);
        if (b >= bstar) {
            int pos = atomicAdd(&sCnt, 1);
            if (pos < 1024)
                sKeys[pos] = ((unsigned long long)v << 32) |
                             (unsigned long long)(0xFFFFFFFFu - (unsigned)ci);
        }
    }
    __syncthreads();
    int cnt = sCnt; if (cnt > 1024) cnt = 1024;
    for (int i = tid; i < 1024; i += 256) if (i >= cnt) sKeys[i] = 0ull;
    __syncthreads();
    for (int size = 2; size <= 1024; size <<= 1) {
        for (int stride = size >> 1; stride > 0; stride >>= 1) {
            for (int t = tid; t < 512; t += 256) {
                int i = ((t & ~(stride - 1)) << 1) | (t & (stride - 1));
                int j = i + stride;
                bool dsc = ((i & size) == 0);
                unsigned long long x = sKeys[i], y = sKeys[j];
                if (dsc == (x < y)) { sKeys[i] = y; sKeys[j] = x; }
            }
            __syncthreads();
        }
    }
    int num = sNum;
    for (int t = tid; t < DD; t += 256) {
        if (t < num) {
            unsigned long long key = sKeys[t];
            int ci = (int)(0xFFFFFFFFu - (unsigned)key);
            int c = ci / KK;
            g_selA[t] = g_anchor[ci];
            out[t * 4 + 0] = g_boxes[ci * 4 + 1];
            out[t * 4 + 1] = g_boxes[ci * 4 + 0];
            out[t * 4 + 2] = g_boxes[ci * 4 + 3];
            out[t * 4 + 3] = g_boxes[ci * 4 + 2];
            out[DD * 4 + t] = __uint_as_float((unsigned)(key >> 32));
            out[DD * 5 + t] = (float)(c + 1);
        } else {
            g_selA[t] = -1;
            out[t * 4 + 0] = 0.f; out[t * 4 + 1] = 0.f;
            out[t * 4 + 2] = 0.f; out[t * 4 + 3] = 0.f;
            out[DD * 4 + t] = 0.f;
            out[DD * 5 + t] = 0.f;
        }
    }
}

// ---------------- K5: logit gather (one block per detection) --------------------
__global__ void k_gather(float* __restrict__ out, const float* __restrict__ logits) {
    int t = blockIdx.x, tid = threadIdx.x;
    int a = g_selA[t];
    if (a >= 0) {
        const float* row = logits + (size_t)a * CC;
        for (int j = tid; j < CC; j += blockDim.x)
            out[DD * 6 + t * CC + j] = row[j];
    } else {
        for (int j = tid; j < CC; j += blockDim.x)
            out[DD * 6 + t * CC + j] = 0.f;
    }
}

extern "C" void kernel_launch(void* const* d_in, const int* in_sizes, int n_in,
                              void* d_out, int out_size) {
    const float* logits = (const float*)d_in[0];
    const float* breg = (const float*)d_in[1];
    const float* anchors = (const float*)d_in[2];
    float* out = (float*)d_out;

    k_zero<<<8, 256>>>();
    k_stats<<<740, 256>>>(logits);
    k_cut<<<NCLS, 96>>>();
    k_topcls<<<NCLS, 256>>>(breg, anchors);
    k_final<<<1, 256>>>(out);
    k_gather<<<DD, 128>>>(out, logits);
}

// round 12
// speedup vs baseline: 2.1797x; 1.0354x over previous
#include <cuda_runtime.h>

#define AA 500000
#define CC 91
#define NCLS 90
#define KK 100
#define DD 200
#define POOLCAP 16384
#define SCAP 1536
#define FCAP 2048
#define HBINS 80
#define HPAD 81
#define HBASE 1968   /* 123<<4 : bins cover p in [2^-4, 2) with 4 mantissa bits */
#define GATE 0.0625f
#define SBINS 1024
#define SBASE 15360
#define SCORE_T 0.01f
#define NMS_T 0.45f
#define NEG_INF -1e30f
#define BBOX_CLIP 4.135166556742356f
#define IMG 512.0f

// ---------------- scratch (static device globals; zero-init at load) ------------
// Invariant: every kernel_launch run leaves g_hist/g_cnt zeroed at the end
// (k_gather tail), so each graph replay starts from the same zero state.
__device__ int   g_hist[NCLS * HBINS];
__device__ int   g_cnt[NCLS];
__device__ unsigned long long g_pool[NCLS * POOLCAP];
__device__ float g_vals[NCLS * KK];
__device__ int   g_anchor[NCLS * KK];
__device__ float g_boxes[NCLS * KK * 4];
__device__ int   g_keptK[NCLS * KK];
__device__ int   g_kc[NCLS];
__device__ int   g_selA[DD];

__device__ __forceinline__ int hbin(float p) {
    int b = (int)(__float_as_uint(p) >> 19) - HBASE;
    return b < 0 ? 0 : (b > HBINS - 1 ? HBINS - 1 : b);
}

// ---------------- K1: fused softmax + histogram + block-staged pooling ----------
struct Stage {
    unsigned long long key[SCAP];
    unsigned char cls[SCAP];
    int top;
    int ccnt[NCLS];
    int base[NCLS];
    int cur[NCLS];
};

__device__ __forceinline__ void push(float p, int r, int a,
                                     unsigned int* sh, Stage* st) {
    if (p > GATE) {
        atomicAdd(&sh[r * HPAD + hbin(p)], 1u);
        unsigned long long key =
            ((unsigned long long)__float_as_uint(p) << 32) | (unsigned)(~(unsigned)a);
        int pos = atomicAdd(&st->top, 1);
        if (pos < SCAP) {
            st->key[pos] = key;
            st->cls[pos] = (unsigned char)r;
            atomicAdd(&st->ccnt[r], 1);
        } else {                                   // rare overflow: direct global
            int gp = atomicAdd(&g_cnt[r], 1);
            if (gp < POOLCAP) g_pool[r * POOLCAP + gp] = key;
        }
    }
}

__global__ void k_stats(const float* __restrict__ logits) {
    __shared__ unsigned int sh[NCLS * HPAD];   // 29160 B, stride 81 -> conflict-free
    __shared__ Stage st;                        // ~14.9 KB
    for (int i = threadIdx.x; i < NCLS * HPAD; i += blockDim.x) sh[i] = 0u;
    for (int i = threadIdx.x; i < NCLS; i += blockDim.x) { st.ccnt[i] = 0; st.cur[i] = 0; }
    if (threadIdx.x == 0) st.top = 0;
    __syncthreads();
    int lane = threadIdx.x & 31;
    int gw = (blockIdx.x * blockDim.x + threadIdx.x) >> 5;
    int nw = (gridDim.x * blockDim.x) >> 5;
    for (int a = gw * 4; a < AA; a += nw * 4) {       // AA % 4 == 0 -> a..a+3 valid
        float e0[4], e1[4], e2[4], s[4];
#pragma unroll
        for (int q = 0; q < 4; q++) {
            const float* r = logits + (size_t)(a + q) * CC;
            float z0 = r[lane], z1 = r[lane + 32];
            e2[q] = (lane < 27) ? __expf(r[lane + 64]) : 0.f;
            e0[q] = __expf(z0);
            e1[q] = __expf(z1);
            s[q] = e0[q] + e1[q] + e2[q];
        }
#pragma unroll
        for (int o = 16; o; o >>= 1) {
#pragma unroll
            for (int q = 0; q < 4; q++)
                s[q] += __shfl_xor_sync(0xffffffffu, s[q], o);
        }
#pragma unroll
        for (int q = 0; q < 4; q++) {
            float inv = __frcp_rn(s[q]);
            if (lane > 0) push(e0[q] * inv, lane - 1, a + q, sh, &st);
            push(e1[q] * inv, lane + 31, a + q, sh, &st);
            if (lane < 27) push(e2[q] * inv, lane + 63, a + q, sh, &st);
        }
    }
    __syncthreads();
    // bulk-reserve pool slots: one global atomic per class per block
    if (threadIdx.x < NCLS) {
        int c = threadIdx.x, n = st.ccnt[c];
        st.base[c] = n ? atomicAdd(&g_cnt[c], n) : 0;
    }
    __syncthreads();
    int top = st.top < SCAP ? st.top : SCAP;
    for (int i = threadIdx.x; i < top; i += blockDim.x) {
        int c = st.cls[i];
        int rk = atomicAdd(&st.cur[c], 1);
        int gp = st.base[c] + rk;
        if (gp < POOLCAP) g_pool[c * POOLCAP + gp] = st.key[i];
    }
    // flush histogram
    for (int i = threadIdx.x; i < NCLS * HPAD; i += blockDim.x) {
        int b = i % HPAD;
        if (b < HBINS) {
            unsigned v = sh[i];
            if (v) atomicAdd(&g_hist[(i / HPAD) * HBINS + b], (int)v);
        }
    }
}

// ---------------- K2: cutoff + filter + topK sort + decode + NMS (fused) --------
__global__ void __launch_bounds__(512) k_topcls(const float* __restrict__ breg,
                                                const float* __restrict__ anchors) {
    __shared__ unsigned long long sk[FCAP];   // 16 KB
    __shared__ float sbx[KK * 4];
    __shared__ unsigned adj[KK * 4];
    __shared__ int h[HBINS];
    __shared__ unsigned sThr;
    __shared__ int sCnt;
    int c = blockIdx.x, tid = threadIdx.x;
    if (tid < HBINS) h[tid] = g_hist[c * HBINS + tid];
    if (tid == 0) sCnt = 0;
    __syncthreads();
    if (tid == 0) {       // per-class cutoff from histogram (was k_cut)
        int cum = 0, cut = 0;
        for (int b = HBINS - 1; b >= 0; --b) {
            cum += h[b];
            if (cum >= KK) { cut = b; break; }
        }
        sThr = (cut <= 0) ? 0u : ((unsigned)(cut + HBASE) << 19);
    }
    __syncthreads();
    unsigned thrBits = sThr;
    int n = g_cnt[c]; if (n > POOLCAP) n = POOLCAP;
    for (int i = tid; i < n; i += 512) {
        unsigned long long key = g_pool[c * POOLCAP + i];
        if ((unsigned)(key >> 32) >= thrBits) {   // exact same bits as histogram
            int pos = atomicAdd(&sCnt, 1);
            if (pos < FCAP) sk[pos] = key;
        }
    }
    __syncthreads();
    int m = sCnt; if (m > FCAP) m = FCAP;
    int npad = 2; while (npad < m) npad <<= 1;
    for (int i = tid; i < npad; i += 512) if (i >= m) sk[i] = 0ull;
    __syncthreads();
    for (int size = 2; size <= npad; size <<= 1) {
        for (int stride = size >> 1; stride > 0; stride >>= 1) {
            for (int t = tid; t < (npad >> 1); t += 512) {
                int i = ((t & ~(stride - 1)) << 1) | (t & (stride - 1));
                int j = i + stride;
                bool dsc = ((i & size) == 0);
                unsigned long long x = sk[i], y = sk[j];
                if (dsc == (x < y)) { sk[i] = y; sk[j] = x; }
            }
            __syncthreads();
        }
    }
    int nv = m < KK ? m : KK;
    for (int k = tid; k < KK; k += 512) {
        float val; int a;
        if (k < nv) {
            unsigned long long key = sk[k];
            val = __uint_as_float((unsigned)(key >> 32));
            a = (int)(~(unsigned)key);
        } else { val = NEG_INF; a = 0; }
        g_vals[c * KK + k] = val;
        g_anchor[c * KK + k] = a;
        float b0 = 0.f, b1 = 0.f, b2 = 0.f, b3 = 0.f;
        if (k < nv) {
            float ax1 = anchors[a * 4 + 0], ay1 = anchors[a * 4 + 1];
            float ax2 = anchors[a * 4 + 2], ay2 = anchors[a * 4 + 3];
            float wa = ax2 - ax1, ha = ay2 - ay1;
            float cxa = ax1 + 0.5f * wa, cya = ay1 + 0.5f * ha;
            float r0 = breg[a * 4 + 0], r1 = breg[a * 4 + 1];
            float r2 = breg[a * 4 + 2], r3 = breg[a * 4 + 3];
            float dx = r0 / 10.0f, dy = r1 / 10.0f;
            float dw = fminf(r2 / 5.0f, BBOX_CLIP), dh = fminf(r3 / 5.0f, BBOX_CLIP);
            float cx = dx * wa + cxa, cy = dy * ha + cya;
            float w = expf(dw) * wa, h2 = expf(dh) * ha;
            b0 = cx - 0.5f * w; b1 = cy - 0.5f * h2;
            b2 = cx + 0.5f * w; b3 = cy + 0.5f * h2;
            b0 = fminf(fmaxf(b0, 0.f), IMG); b1 = fminf(fmaxf(b1, 0.f), IMG);
            b2 = fminf(fmaxf(b2, 0.f), IMG); b3 = fminf(fmaxf(b3, 0.f), IMG);
        }
        g_boxes[(c * KK + k) * 4 + 0] = b0;  sbx[k * 4 + 0] = b0;
        g_boxes[(c * KK + k) * 4 + 1] = b1;  sbx[k * 4 + 1] = b1;
        g_boxes[(c * KK + k) * 4 + 2] = b2;  sbx[k * 4 + 2] = b2;
        g_boxes[(c * KK + k) * 4 + 3] = b3;  sbx[k * 4 + 3] = b3;
    }
    __syncthreads();
    // IoU adjacency bitmap (within-class: label offset cancels exactly)
    for (int idx = tid; idx < KK * 4; idx += 512) {
        int i = idx >> 2, w = idx & 3;
        unsigned mask = 0u;
        if (i < nv) {
            float ix1 = sbx[i * 4 + 0], iy1 = sbx[i * 4 + 1];
            float ix2 = sbx[i * 4 + 2], iy2 = sbx[i * 4 + 3];
            float areai = (ix2 - ix1) * (iy2 - iy1);
            int j0 = w * 32;
            int jend = nv - j0; if (jend > 32) jend = 32;
            for (int b = 0; b < jend; b++) {
                int j = j0 + b;
                float jx1 = sbx[j * 4 + 0], jy1 = sbx[j * 4 + 1];
                float jx2 = sbx[j * 4 + 2], jy2 = sbx[j * 4 + 3];
                float ltx = fmaxf(ix1, jx1), lty = fmaxf(iy1, jy1);
                float rbx = fminf(ix2, jx2), rby = fminf(iy2, jy2);
                float w2 = fmaxf(rbx - ltx, 0.f), hh = fmaxf(rby - lty, 0.f);
                float inter = w2 * hh;
                float areaj = (jx2 - jx1) * (jy2 - jy1);
                float iou = inter / fmaxf(areai + areaj - inter, 1e-9f);
                if (iou > NMS_T) mask |= (1u << b);
            }
        }
        adj[idx] = mask;
    }
    __syncthreads();
    if (tid == 0) {
        unsigned supp[4];
#pragma unroll
        for (int w = 0; w < 4; w++) {
            int lo = w * 32;
            if (nv >= lo + 32) supp[w] = 0u;
            else if (nv <= lo) supp[w] = 0xFFFFFFFFu;
            else supp[w] = ~((1u << (nv - lo)) - 1u);
        }
        int kc = 0;
        for (int i = 0; i < KK; i++) {
            if (!((supp[i >> 5] >> (i & 31)) & 1u)) {
                g_keptK[c * KK + kc++] = i;
                supp[0] |= adj[i * 4 + 0]; supp[1] |= adj[i * 4 + 1];
                supp[2] |= adj[i * 4 + 2]; supp[3] |= adj[i * 4 + 3];
            }
        }
        g_kc[c] = kc;
    }
}

// ---------------- K3: global top-D select + scalar outputs ----------------------
__global__ void k_final(float* __restrict__ out) {
    __shared__ int sPref[NCLS + 1];
    __shared__ int sHist[SBINS];
    __shared__ unsigned long long sKeys[1024];
    __shared__ int sCnt, sB, sNum;
    int tid = threadIdx.x;  // 256
    for (int i = tid; i < SBINS; i += 256) sHist[i] = 0;
    if (tid < NCLS) sPref[tid + 1] = g_kc[tid];
    if (tid == 0) { sPref[0] = 0; sCnt = 0; }
    __syncthreads();
    if (tid == 0)
        for (int c = 1; c <= NCLS; c++) sPref[c] += sPref[c - 1];
    __syncthreads();
    int tot = sPref[NCLS];
    for (int g = tid; g < tot; g += 256) {
        int lo = 0, hi = NCLS;
        while (hi - lo > 1) { int mid = (lo + hi) >> 1; if (sPref[mid] <= g) lo = mid; else hi = mid; }
        int c = lo, j = g - sPref[c];
        int k = g_keptK[c * KK + j];
        unsigned v = __float_as_uint(g_vals[c * KK + k]);
        int b = (int)(v >> 16) - SBASE;
        b = b < 0 ? 0 : (b > SBINS - 1 ? SBINS - 1 : b);
        atomicAdd(&sHist[b], 1);
    }
    __syncthreads();
    int r = tot < DD ? tot : DD;
    if (tid == 0) {
        int cum = 0, b = 0;
        for (int i = SBINS - 1; i >= 0; --i) { cum += sHist[i]; if (cum >= r) { b = i; break; } }
        sB = (r > 0) ? b : SBINS;
        sNum = r;
    }
    __syncthreads();
    int bstar = sB;
    for (int g = tid; g < tot; g += 256) {
        int lo = 0, hi = NCLS;
        while (hi - lo > 1) { int mid = (lo + hi) >> 1; if (sPref[mid] <= g) lo = mid; else hi = mid; }
        int c = lo, j = g - sPref[c];
        int k = g_keptK[c * KK + j];
        int ci = c * KK + k;
        unsigned v = __float_as_uint(g_vals[ci]);
        int b = (int)(v >> 16) - SBASE;
        b = b < 0 ? 0 : (b > SBINS - 1 ? SBINS - 1 : b);
        if (b >= bstar) {
            int pos = atomicAdd(&sCnt, 1);
            if (pos < 1024)
                sKeys[pos] = ((unsigned long long)v << 32) |
                             (unsigned long long)(0xFFFFFFFFu - (unsigned)ci);
        }
    }
    __syncthreads();
    int cnt = sCnt; if (cnt > 1024) cnt = 1024;
    int npad = 2; while (npad < cnt) npad <<= 1;     // adaptive sort width
    for (int i = tid; i < npad; i += 256) if (i >= cnt) sKeys[i] = 0ull;
    __syncthreads();
    for (int size = 2; size <= npad; size <<= 1) {
        for (int stride = size >> 1; stride > 0; stride >>= 1) {
            for (int t = tid; t < (npad >> 1); t += 256) {
                int i = ((t & ~(stride - 1)) << 1) | (t & (stride - 1));
                int j = i + stride;
                bool dsc = ((i & size) == 0);
                unsigned long long x = sKeys[i], y = sKeys[j];
                if (dsc == (x < y)) { sKeys[i] = y; sKeys[j] = x; }
            }
            __syncthreads();
        }
    }
    int num = sNum;
    for (int t = tid; t < DD; t += 256) {
        if (t < num) {
            unsigned long long key = sKeys[t];
            int ci = (int)(0xFFFFFFFFu - (unsigned)key);
            int c = ci / KK;
            g_selA[t] = g_anchor[ci];
            out[t * 4 + 0] = g_boxes[ci * 4 + 1];
            out[t * 4 + 1] = g_boxes[ci * 4 + 0];
            out[t * 4 + 2] = g_boxes[ci * 4 + 3];
            out[t * 4 + 3] = g_boxes[ci * 4 + 2];
            out[DD * 4 + t] = __uint_as_float((unsigned)(key >> 32));
            out[DD * 5 + t] = (float)(c + 1);
        } else {
            g_selA[t] = -1;
            out[t * 4 + 0] = 0.f; out[t * 4 + 1] = 0.f;
            out[t * 4 + 2] = 0.f; out[t * 4 + 3] = 0.f;
            out[DD * 4 + t] = 0.f;
            out[DD * 5 + t] = 0.f;
        }
    }
}

// ---------------- K4: logit gather + reset state for next replay ----------------
__global__ void k_gather(float* __restrict__ out, const float* __restrict__ logits) {
    int t = blockIdx.x, tid = threadIdx.x;
    int a = g_selA[t];
    if (a >= 0) {
        const float* row = logits + (size_t)a * CC;
        for (int j = tid; j < CC; j += blockDim.x)
            out[DD * 6 + t * CC + j] = row[j];
    } else {
        for (int j = tid; j < CC; j += blockDim.x)
            out[DD * 6 + t * CC + j] = 0.f;
    }
    // zero per-launch state (every run ends zeroed; replays start zeroed)
    int gt = blockIdx.x * blockDim.x + tid;            // 200*128 = 25600 threads
    if (gt < NCLS * HBINS) g_hist[gt] = 0;             // 7200 ints
    if (gt >= NCLS * HBINS && gt < NCLS * HBINS + NCLS) g_cnt[gt - NCLS * HBINS] = 0;
}

extern "C" void kernel_launch(void* const* d_in, const int* in_sizes, int n_in,
                              void* d_out, int out_size) {
    const float* logits = (const float*)d_in[0];
    const float* breg = (const float*)d_in[1];
    const float* anchors = (const float*)d_in[2];
    float* out = (float*)d_out;

    k_stats<<<444, 256>>>(logits);
    k_topcls<<<NCLS, 512>>>(breg, anchors);
    k_final<<<1, 256>>>(out);
    k_gather<<<DD, 128>>>(out, logits);
}

// round 13
// speedup vs baseline: 2.4326x; 1.1160x over previous
#include <cuda_runtime.h>

#define AA 500000
#define CC 91
#define NCLS 90
#define KK 100
#define DD 200
#define POOLCAP 16384
#define SCAP 1536
#define FCAP 2048
#define HBINS 80
#define HBASE 1968   /* 123<<4 : bins cover p in [2^-4, 2) with 4 mantissa bits */
#define GATE 0.0625f
#define SBINS 1024
#define SBASE 15360
#define SCORE_T 0.01f
#define NMS_T 0.45f
#define NEG_INF -1e30f
#define BBOX_CLIP 4.135166556742356f
#define IMG 512.0f

// ---------------- scratch (static device globals; zero-init at load) ------------
// Invariant: every run leaves g_cnt zeroed (k_gather tail) so replays start clean.
__device__ int   g_cnt[NCLS];
__device__ unsigned long long g_pool[NCLS * POOLCAP];
__device__ float g_vals[NCLS * KK];
__device__ int   g_anchor[NCLS * KK];
__device__ float g_boxes[NCLS * KK * 4];
__device__ int   g_keptK[NCLS * KK];
__device__ int   g_kc[NCLS];
__device__ int   g_selA[DD];

// ---------------- K1: fused softmax + block-staged pooling (no histogram) -------
struct Stage {
    unsigned long long key[SCAP];
    unsigned char cls[SCAP];
    int top;
    int ccnt[NCLS];
    int base[NCLS];
    int cur[NCLS];
};

__device__ __forceinline__ void push(float p, int r, int a, Stage* st) {
    if (p > GATE) {
        unsigned long long key =
            ((unsigned long long)__float_as_uint(p) << 32) | (unsigned)(~(unsigned)a);
        int pos = atomicAdd(&st->top, 1);
        if (pos < SCAP) {
            st->key[pos] = key;
            st->cls[pos] = (unsigned char)r;
            atomicAdd(&st->ccnt[r], 1);
        } else {                                   // rare overflow: direct global
            int gp = atomicAdd(&g_cnt[r], 1);
            if (gp < POOLCAP) g_pool[r * POOLCAP + gp] = key;
        }
    }
}

__global__ void __launch_bounds__(256, 4) k_stats(const float* __restrict__ logits) {
    __shared__ Stage st;                        // ~14.6 KB
    for (int i = threadIdx.x; i < NCLS; i += blockDim.x) { st.ccnt[i] = 0; st.cur[i] = 0; }
    if (threadIdx.x == 0) st.top = 0;
    __syncthreads();
    int lane = threadIdx.x & 31;
    int gw = (blockIdx.x * blockDim.x + threadIdx.x) >> 5;
    int nw = (gridDim.x * blockDim.x) >> 5;
    for (int a = gw * 4; a < AA; a += nw * 4) {       // AA % 4 == 0 -> a..a+3 valid
        float e0[4], e1[4], e2[4], s[4];
#pragma unroll
        for (int q = 0; q < 4; q++) {
            const float* r = logits + (size_t)(a + q) * CC;
            float z0 = r[lane], z1 = r[lane + 32];
            e2[q] = (lane < 27) ? __expf(r[lane + 64]) : 0.f;
            e0[q] = __expf(z0);
            e1[q] = __expf(z1);
            s[q] = e0[q] + e1[q] + e2[q];
        }
#pragma unroll
        for (int o = 16; o; o >>= 1) {
#pragma unroll
            for (int q = 0; q < 4; q++)
                s[q] += __shfl_xor_sync(0xffffffffu, s[q], o);
        }
#pragma unroll
        for (int q = 0; q < 4; q++) {
            float inv = __frcp_rn(s[q]);
            if (lane > 0) push(e0[q] * inv, lane - 1, a + q, &st);
            push(e1[q] * inv, lane + 31, a + q, &st);
            if (lane < 27) push(e2[q] * inv, lane + 63, a + q, &st);
        }
    }
    __syncthreads();
    // bulk-reserve pool slots: one global atomic per class per block
    if (threadIdx.x < NCLS) {
        int c = threadIdx.x, n = st.ccnt[c];
        st.base[c] = n ? atomicAdd(&g_cnt[c], n) : 0;
    }
    __syncthreads();
    int top = st.top < SCAP ? st.top : SCAP;
    for (int i = threadIdx.x; i < top; i += blockDim.x) {
        int c = st.cls[i];
        int rk = atomicAdd(&st.cur[c], 1);
        int gp = st.base[c] + rk;
        if (gp < POOLCAP) g_pool[c * POOLCAP + gp] = st.key[i];
    }
}

// ---------------- K2: pool hist + cutoff + topK sort + decode + NMS (fused) -----
__global__ void __launch_bounds__(512) k_topcls(const float* __restrict__ breg,
                                                const float* __restrict__ anchors) {
    __shared__ unsigned long long sk[FCAP];   // 16 KB
    __shared__ float sbx[KK * 4];
    __shared__ unsigned adj[KK * 4];
    __shared__ int h[HBINS];
    __shared__ unsigned sThr;
    __shared__ int sCnt;
    int c = blockIdx.x, tid = threadIdx.x;
    if (tid < HBINS) h[tid] = 0;
    if (tid == 0) sCnt = 0;
    __syncthreads();
    int n = g_cnt[c]; if (n > POOLCAP) n = POOLCAP;
    // pass 1: build 80-bin histogram from this class's pool
    for (int i = tid; i < n; i += 512) {
        unsigned bits = (unsigned)(g_pool[c * POOLCAP + i] >> 32);
        int b = (int)(bits >> 19) - HBASE;
        b = b < 0 ? 0 : (b > HBINS - 1 ? HBINS - 1 : b);
        atomicAdd(&h[b], 1);
    }
    __syncthreads();
    if (tid == 0) {       // per-class cutoff
        int cum = 0, cut = 0;
        for (int b = HBINS - 1; b >= 0; --b) {
            cum += h[b];
            if (cum >= KK) { cut = b; break; }
        }
        sThr = (cut <= 0) ? 0u : ((unsigned)(cut + HBASE) << 19);
    }
    __syncthreads();
    unsigned thrBits = sThr;
    // pass 2: collect keys at/above cutoff (L2-hot re-read)
    for (int i = tid; i < n; i += 512) {
        unsigned long long key = g_pool[c * POOLCAP + i];
        if ((unsigned)(key >> 32) >= thrBits) {
            int pos = atomicAdd(&sCnt, 1);
            if (pos < FCAP) sk[pos] = key;
        }
    }
    __syncthreads();
    int m = sCnt; if (m > FCAP) m = FCAP;
    int npad = 2; while (npad < m) npad <<= 1;
    for (int i = tid; i < npad; i += 512) if (i >= m) sk[i] = 0ull;
    __syncthreads();
    for (int size = 2; size <= npad; size <<= 1) {
        for (int stride = size >> 1; stride > 0; stride >>= 1) {
            for (int t = tid; t < (npad >> 1); t += 512) {
                int i = ((t & ~(stride - 1)) << 1) | (t & (stride - 1));
                int j = i + stride;
                bool dsc = ((i & size) == 0);
                unsigned long long x = sk[i], y = sk[j];
                if (dsc == (x < y)) { sk[i] = y; sk[j] = x; }
            }
            __syncthreads();
        }
    }
    int nv = m < KK ? m : KK;
    for (int k = tid; k < KK; k += 512) {
        float val; int a;
        if (k < nv) {
            unsigned long long key = sk[k];
            val = __uint_as_float((unsigned)(key >> 32));
            a = (int)(~(unsigned)key);
        } else { val = NEG_INF; a = 0; }
        g_vals[c * KK + k] = val;
        g_anchor[c * KK + k] = a;
        float b0 = 0.f, b1 = 0.f, b2 = 0.f, b3 = 0.f;
        if (k < nv) {
            float ax1 = anchors[a * 4 + 0], ay1 = anchors[a * 4 + 1];
            float ax2 = anchors[a * 4 + 2], ay2 = anchors[a * 4 + 3];
            float wa = ax2 - ax1, ha = ay2 - ay1;
            float cxa = ax1 + 0.5f * wa, cya = ay1 + 0.5f * ha;
            float r0 = breg[a * 4 + 0], r1 = breg[a * 4 + 1];
            float r2 = breg[a * 4 + 2], r3 = breg[a * 4 + 3];
            float dx = r0 / 10.0f, dy = r1 / 10.0f;
            float dw = fminf(r2 / 5.0f, BBOX_CLIP), dh = fminf(r3 / 5.0f, BBOX_CLIP);
            float cx = dx * wa + cxa, cy = dy * ha + cya;
            float w = expf(dw) * wa, h2 = expf(dh) * ha;
            b0 = cx - 0.5f * w; b1 = cy - 0.5f * h2;
            b2 = cx + 0.5f * w; b3 = cy + 0.5f * h2;
            b0 = fminf(fmaxf(b0, 0.f), IMG); b1 = fminf(fmaxf(b1, 0.f), IMG);
            b2 = fminf(fmaxf(b2, 0.f), IMG); b3 = fminf(fmaxf(b3, 0.f), IMG);
        }
        g_boxes[(c * KK + k) * 4 + 0] = b0;  sbx[k * 4 + 0] = b0;
        g_boxes[(c * KK + k) * 4 + 1] = b1;  sbx[k * 4 + 1] = b1;
        g_boxes[(c * KK + k) * 4 + 2] = b2;  sbx[k * 4 + 2] = b2;
        g_boxes[(c * KK + k) * 4 + 3] = b3;  sbx[k * 4 + 3] = b3;
    }
    __syncthreads();
    // IoU adjacency bitmap (within-class: label offset cancels exactly)
    for (int idx = tid; idx < KK * 4; idx += 512) {
        int i = idx >> 2, w = idx & 3;
        unsigned mask = 0u;
        if (i < nv) {
            float ix1 = sbx[i * 4 + 0], iy1 = sbx[i * 4 + 1];
            float ix2 = sbx[i * 4 + 2], iy2 = sbx[i * 4 + 3];
            float areai = (ix2 - ix1) * (iy2 - iy1);
            int j0 = w * 32;
            int jend = nv - j0; if (jend > 32) jend = 32;
            for (int b = 0; b < jend; b++) {
                int j = j0 + b;
                float jx1 = sbx[j * 4 + 0], jy1 = sbx[j * 4 + 1];
                float jx2 = sbx[j * 4 + 2], jy2 = sbx[j * 4 + 3];
                float ltx = fmaxf(ix1, jx1), lty = fmaxf(iy1, jy1);
                float rbx = fminf(ix2, jx2), rby = fminf(iy2, jy2);
                float w2 = fmaxf(rbx - ltx, 0.f), hh = fmaxf(rby - lty, 0.f);
                float inter = w2 * hh;
                float areaj = (jx2 - jx1) * (jy2 - jy1);
                float iou = inter / fmaxf(areai + areaj - inter, 1e-9f);
                if (iou > NMS_T) mask |= (1u << b);
            }
        }
        adj[idx] = mask;
    }
    __syncthreads();
    if (tid == 0) {
        unsigned supp[4];
#pragma unroll
        for (int w = 0; w < 4; w++) {
            int lo = w * 32;
            if (nv >= lo + 32) supp[w] = 0u;
            else if (nv <= lo) supp[w] = 0xFFFFFFFFu;
            else supp[w] = ~((1u << (nv - lo)) - 1u);
        }
        int kc = 0;
        for (int i = 0; i < KK; i++) {
            if (!((supp[i >> 5] >> (i & 31)) & 1u)) {
                g_keptK[c * KK + kc++] = i;
                supp[0] |= adj[i * 4 + 0]; supp[1] |= adj[i * 4 + 1];
                supp[2] |= adj[i * 4 + 2]; supp[3] |= adj[i * 4 + 3];
            }
        }
        g_kc[c] = kc;
    }
}

// ---------------- K3: global top-D select + scalar outputs ----------------------
__global__ void k_final(float* __restrict__ out) {
    __shared__ int sPref[NCLS + 1];
    __shared__ int sHist[SBINS];
    __shared__ unsigned long long sKeys[1024];
    __shared__ int sCnt, sB, sNum;
    int tid = threadIdx.x;  // 256
    for (int i = tid; i < SBINS; i += 256) sHist[i] = 0;
    if (tid < NCLS) sPref[tid + 1] = g_kc[tid];
    if (tid == 0) { sPref[0] = 0; sCnt = 0; }
    __syncthreads();
    // Hillis-Steele inclusive scan over sPref[1..NCLS]
    for (int off = 1; off <= NCLS; off <<= 1) {
        int v = 0;
        if (tid <= NCLS && tid >= off) v = sPref[tid - off];
        __syncthreads();
        if (tid <= NCLS && tid >= off) sPref[tid] += v;
        __syncthreads();
    }
    int tot = sPref[NCLS];
    for (int g = tid; g < tot; g += 256) {
        int lo = 0, hi = NCLS;
        while (hi - lo > 1) { int mid = (lo + hi) >> 1; if (sPref[mid] <= g) lo = mid; else hi = mid; }
        int c = lo, j = g - sPref[c];
        int k = g_keptK[c * KK + j];
        unsigned v = __float_as_uint(g_vals[c * KK + k]);
        int b = (int)(v >> 16) - SBASE;
        b = b < 0 ? 0 : (b > SBINS - 1 ? SBINS - 1 : b);
        atomicAdd(&sHist[b], 1);
    }
    __syncthreads();
    int r = tot < DD ? tot : DD;
    if (tid == 0) {
        int cum = 0, b = 0;
        for (int i = SBINS - 1; i >= 0; --i) { cum += sHist[i]; if (cum >= r) { b = i; break; } }
        sB = (r > 0) ? b : SBINS;
        sNum = r;
    }
    __syncthreads();
    int bstar = sB;
    for (int g = tid; g < tot; g += 256) {
        int lo = 0, hi = NCLS;
        while (hi - lo > 1) { int mid = (lo + hi) >> 1; if (sPref[mid] <= g) lo = mid; else hi = mid; }
        int c = lo, j = g - sPref[c];
        int k = g_keptK[c * KK + j];
        int ci = c * KK + k;
        unsigned v = __float_as_uint(g_vals[ci]);
        int b = (int)(v >> 16) - SBASE;
        b = b < 0 ? 0 : (b > SBINS - 1 ? SBINS - 1 : b);
        if (b >= bstar) {
            int pos = atomicAdd(&sCnt, 1);
            if (pos < 1024)
                sKeys[pos] = ((unsigned long long)v << 32) |
                             (unsigned long long)(0xFFFFFFFFu - (unsigned)ci);
        }
    }
    __syncthreads();
    int cnt = sCnt; if (cnt > 1024) cnt = 1024;
    int npad = 2; while (npad < cnt) npad <<= 1;     // adaptive sort width
    for (int i = tid; i < npad; i += 256) if (i >= cnt) sKeys[i] = 0ull;
    __syncthreads();
    for (int size = 2; size <= npad; size <<= 1) {
        for (int stride = size >> 1; stride > 0; stride >>= 1) {
            for (int t = tid; t < (npad >> 1); t += 256) {
                int i = ((t & ~(stride - 1)) << 1) | (t & (stride - 1));
                int j = i + stride;
                bool dsc = ((i & size) == 0);
                unsigned long long x = sKeys[i], y = sKeys[j];
                if (dsc == (x < y)) { sKeys[i] = y; sKeys[j] = x; }
            }
            __syncthreads();
        }
    }
    int num = sNum;
    for (int t = tid; t < DD; t += 256) {
        if (t < num) {
            unsigned long long key = sKeys[t];
            int ci = (int)(0xFFFFFFFFu - (unsigned)key);
            int c = ci / KK;
            g_selA[t] = g_anchor[ci];
            out[t * 4 + 0] = g_boxes[ci * 4 + 1];
            out[t * 4 + 1] = g_boxes[ci * 4 + 0];
            out[t * 4 + 2] = g_boxes[ci * 4 + 3];
            out[t * 4 + 3] = g_boxes[ci * 4 + 2];
            out[DD * 4 + t] = __uint_as_float((unsigned)(key >> 32));
            out[DD * 5 + t] = (float)(c + 1);
        } else {
            g_selA[t] = -1;
            out[t * 4 + 0] = 0.f; out[t * 4 + 1] = 0.f;
            out[t * 4 + 2] = 0.f; out[t * 4 + 3] = 0.f;
            out[DD * 4 + t] = 0.f;
            out[DD * 5 + t] = 0.f;
        }
    }
}

// ---------------- K4: logit gather + reset state for next replay ----------------
__global__ void k_gather(float* __restrict__ out, const float* __restrict__ logits) {
    int t = blockIdx.x, tid = threadIdx.x;
    int a = g_selA[t];
    if (a >= 0) {
        const float* row = logits + (size_t)a * CC;
        for (int j = tid; j < CC; j += blockDim.x)
            out[DD * 6 + t * CC + j] = row[j];
    } else {
        for (int j = tid; j < CC; j += blockDim.x)
            out[DD * 6 + t * CC + j] = 0.f;
    }
    // zero per-launch state (every run ends zeroed; replays start zeroed)
    int gt = blockIdx.x * blockDim.x + tid;
    if (gt < NCLS) g_cnt[gt] = 0;
}

extern "C" void kernel_launch(void* const* d_in, const int* in_sizes, int n_in,
                              void* d_out, int out_size) {
    const float* logits = (const float*)d_in[0];
    const float* breg = (const float*)d_in[1];
    const float* anchors = (const float*)d_in[2];
    float* out = (float*)d_out;

    k_stats<<<592, 256>>>(logits);
    k_topcls<<<NCLS, 512>>>(breg, anchors);
    k_final<<<1, 256>>>(out);
    k_gather<<<DD, 128>>>(out, logits);
}

// round 14
// speedup vs baseline: 2.9356x; 1.2068x over previous
#include <cuda_runtime.h>

#define AA 500000
#define CC 91
#define NCLS 90
#define KK 100
#define DD 200
#define POOLCAP 16384
#define SCAP 1536
#define FCAP 2048
#define HBINS 80
#define HBASE 1968   /* 123<<4 : bins cover p in [2^-4, 2) with 4 mantissa bits */
#define GATE 0.0625f
#define SBINS 1024
#define SBASE 15360
#define SCORE_T 0.01f
#define NMS_T 0.45f
#define NEG_INF -1e30f
#define BBOX_CLIP 4.135166556742356f
#define IMG 512.0f

// ---------------- scratch (static device globals; zero-init at load) ------------
// g_cnt zeroed at end of k_tail; g_bar1/g_bar2 zeroed at start of k_stats.
__device__ int   g_cnt[NCLS];
__device__ unsigned long long g_pool[NCLS * POOLCAP];
__device__ float g_vals[NCLS * KK];
__device__ int   g_anchor[NCLS * KK];
__device__ float g_boxes[NCLS * KK * 4];
__device__ int   g_keptK[NCLS * KK];
__device__ int   g_kc[NCLS];
__device__ int   g_selA[DD];
__device__ int   g_bar1;
__device__ int   g_bar2;

// ---------------- K1: fused softmax + block-staged pooling ----------------------
struct Stage {
    unsigned long long key[SCAP];
    unsigned char cls[SCAP];
    int top;
    int ccnt[NCLS];
    int base[NCLS];
    int cur[NCLS];
};

__device__ __forceinline__ void push(float p, int r, int a, Stage* st) {
    unsigned long long key =
        ((unsigned long long)__float_as_uint(p) << 32) | (unsigned)(~(unsigned)a);
    int pos = atomicAdd(&st->top, 1);
    if (pos < SCAP) {
        st->key[pos] = key;
        st->cls[pos] = (unsigned char)r;
        atomicAdd(&st->ccnt[r], 1);
    } else {                                   // rare overflow: direct global
        int gp = atomicAdd(&g_cnt[r], 1);
        if (gp < POOLCAP) g_pool[r * POOLCAP + gp] = key;
    }
}

__global__ void __launch_bounds__(256, 4) k_stats(const float* __restrict__ logits) {
    __shared__ Stage st;                        // ~14.6 KB
    for (int i = threadIdx.x; i < NCLS; i += blockDim.x) { st.ccnt[i] = 0; st.cur[i] = 0; }
    if (threadIdx.x == 0) st.top = 0;
    if (blockIdx.x == 0 && threadIdx.x == 0) { g_bar1 = 0; g_bar2 = 0; }  // reset tail barriers
    __syncthreads();
    int lane = threadIdx.x & 31;
    int gw = (blockIdx.x * blockDim.x + threadIdx.x) >> 5;
    int nw = (gridDim.x * blockDim.x) >> 5;
    for (int a = gw * 4; a < AA; a += nw * 4) {       // AA % 4 == 0 -> a..a+3 valid
        float e0[4], e1[4], e2[4], s[4];
#pragma unroll
        for (int q = 0; q < 4; q++) {
            const float* r = logits + (size_t)(a + q) * CC;
            float z0 = r[lane], z1 = r[lane + 32];
            e2[q] = (lane < 27) ? __expf(r[lane + 64]) : 0.f;
            e0[q] = __expf(z0);
            e1[q] = __expf(z1);
            s[q] = e0[q] + e1[q] + e2[q];
        }
#pragma unroll
        for (int o = 16; o; o >>= 1) {
#pragma unroll
            for (int q = 0; q < 4; q++)
                s[q] += __shfl_xor_sync(0xffffffffu, s[q], o);
        }
#pragma unroll
        for (int q = 0; q < 4; q++) {
            float thrE = s[q] * GATE;            // e > GATE*s  <=>  p > GATE
            bool c0 = (lane > 0) && (e0[q] > thrE);
            bool c1 = e1[q] > thrE;
            bool c2 = (lane < 27) && (e2[q] > thrE);
            if (c0 | c1 | c2) {                  // rare (~1.2% of rows)
                float inv = __frcp_rn(s[q]);
                if (c0) push(e0[q] * inv, lane - 1, a + q, &st);
                if (c1) push(e1[q] * inv, lane + 31, a + q, &st);
                if (c2) push(e2[q] * inv, lane + 63, a + q, &st);
            }
        }
    }
    __syncthreads();
    // bulk-reserve pool slots: one global atomic per class per block
    if (threadIdx.x < NCLS) {
        int c = threadIdx.x, n = st.ccnt[c];
        st.base[c] = n ? atomicAdd(&g_cnt[c], n) : 0;
    }
    __syncthreads();
    int top = st.top < SCAP ? st.top : SCAP;
    for (int i = threadIdx.x; i < top; i += blockDim.x) {
        int c = st.cls[i];
        int rk = atomicAdd(&st.cur[c], 1);
        int gp = st.base[c] + rk;
        if (gp < POOLCAP) g_pool[c * POOLCAP + gp] = st.key[i];
    }
}

// ---------------- K2: persistent tail — topcls + final + gather -----------------
// 90 blocks x 512 threads, all resident (90 < 148 SMs). Global spin barriers.
__global__ void __launch_bounds__(512) k_tail(const float* __restrict__ breg,
                                              const float* __restrict__ anchors,
                                              float* __restrict__ out,
                                              const float* __restrict__ logits) {
    __shared__ unsigned long long sk[FCAP];   // 16 KB (phase A)
    __shared__ float sbx[KK * 4];
    __shared__ unsigned adj[KK * 4];
    __shared__ int h[HBINS];
    __shared__ unsigned sThr;
    __shared__ int sCnt;
    // phase-B storage (block 0 only; coexists within 48 KB)
    __shared__ int sPref[NCLS + 1];
    __shared__ int sHist[SBINS];
    __shared__ unsigned long long sKeys[1024];
    __shared__ int sB, sNum;

    int c = blockIdx.x, tid = threadIdx.x;

    // ================= Phase A: per-class topcls =================
    if (tid < HBINS) h[tid] = 0;
    if (tid == 0) sCnt = 0;
    __syncthreads();
    int n = g_cnt[c]; if (n > POOLCAP) n = POOLCAP;
    for (int i = tid; i < n; i += 512) {
        unsigned bits = (unsigned)(g_pool[c * POOLCAP + i] >> 32);
        int b = (int)(bits >> 19) - HBASE;
        b = b < 0 ? 0 : (b > HBINS - 1 ? HBINS - 1 : b);
        atomicAdd(&h[b], 1);
    }
    __syncthreads();
    if (tid == 0) {       // per-class cutoff
        int cum = 0, cut = 0;
        for (int b = HBINS - 1; b >= 0; --b) {
            cum += h[b];
            if (cum >= KK) { cut = b; break; }
        }
        sThr = (cut <= 0) ? 0u : ((unsigned)(cut + HBASE) << 19);
    }
    __syncthreads();
    unsigned thrBits = sThr;
    for (int i = tid; i < n; i += 512) {
        unsigned long long key = g_pool[c * POOLCAP + i];
        if ((unsigned)(key >> 32) >= thrBits) {
            int pos = atomicAdd(&sCnt, 1);
            if (pos < FCAP) sk[pos] = key;
        }
    }
    __syncthreads();
    int m = sCnt; if (m > FCAP) m = FCAP;
    int npad = 2; while (npad < m) npad <<= 1;
    for (int i = tid; i < npad; i += 512) if (i >= m) sk[i] = 0ull;
    __syncthreads();
    for (int size = 2; size <= npad; size <<= 1) {
        for (int stride = size >> 1; stride > 0; stride >>= 1) {
            for (int t = tid; t < (npad >> 1); t += 512) {
                int i = ((t & ~(stride - 1)) << 1) | (t & (stride - 1));
                int j = i + stride;
                bool dsc = ((i & size) == 0);
                unsigned long long x = sk[i], y = sk[j];
                if (dsc == (x < y)) { sk[i] = y; sk[j] = x; }
            }
            __syncthreads();
        }
    }
    int nv = m < KK ? m : KK;
    for (int k = tid; k < KK; k += 512) {
        float val; int a;
        if (k < nv) {
            unsigned long long key = sk[k];
            val = __uint_as_float((unsigned)(key >> 32));
            a = (int)(~(unsigned)key);
        } else { val = NEG_INF; a = 0; }
        g_vals[c * KK + k] = val;
        g_anchor[c * KK + k] = a;
        float b0 = 0.f, b1 = 0.f, b2 = 0.f, b3 = 0.f;
        if (k < nv) {
            float ax1 = anchors[a * 4 + 0], ay1 = anchors[a * 4 + 1];
            float ax2 = anchors[a * 4 + 2], ay2 = anchors[a * 4 + 3];
            float wa = ax2 - ax1, ha = ay2 - ay1;
            float cxa = ax1 + 0.5f * wa, cya = ay1 + 0.5f * ha;
            float r0 = breg[a * 4 + 0], r1 = breg[a * 4 + 1];
            float r2 = breg[a * 4 + 2], r3 = breg[a * 4 + 3];
            float dx = r0 / 10.0f, dy = r1 / 10.0f;
            float dw = fminf(r2 / 5.0f, BBOX_CLIP), dh = fminf(r3 / 5.0f, BBOX_CLIP);
            float cx = dx * wa + cxa, cy = dy * ha + cya;
            float w = expf(dw) * wa, h2 = expf(dh) * ha;
            b0 = cx - 0.5f * w; b1 = cy - 0.5f * h2;
            b2 = cx + 0.5f * w; b3 = cy + 0.5f * h2;
            b0 = fminf(fmaxf(b0, 0.f), IMG); b1 = fminf(fmaxf(b1, 0.f), IMG);
            b2 = fminf(fmaxf(b2, 0.f), IMG); b3 = fminf(fmaxf(b3, 0.f), IMG);
        }
        g_boxes[(c * KK + k) * 4 + 0] = b0;  sbx[k * 4 + 0] = b0;
        g_boxes[(c * KK + k) * 4 + 1] = b1;  sbx[k * 4 + 1] = b1;
        g_boxes[(c * KK + k) * 4 + 2] = b2;  sbx[k * 4 + 2] = b2;
        g_boxes[(c * KK + k) * 4 + 3] = b3;  sbx[k * 4 + 3] = b3;
    }
    __syncthreads();
    for (int idx = tid; idx < KK * 4; idx += 512) {
        int i = idx >> 2, w = idx & 3;
        unsigned mask = 0u;
        if (i < nv) {
            float ix1 = sbx[i * 4 + 0], iy1 = sbx[i * 4 + 1];
            float ix2 = sbx[i * 4 + 2], iy2 = sbx[i * 4 + 3];
            float areai = (ix2 - ix1) * (iy2 - iy1);
            int j0 = w * 32;
            int jend = nv - j0; if (jend > 32) jend = 32;
            for (int b = 0; b < jend; b++) {
                int j = j0 + b;
                float jx1 = sbx[j * 4 + 0], jy1 = sbx[j * 4 + 1];
                float jx2 = sbx[j * 4 + 2], jy2 = sbx[j * 4 + 3];
                float ltx = fmaxf(ix1, jx1), lty = fmaxf(iy1, jy1);
                float rbx = fminf(ix2, jx2), rby = fminf(iy2, jy2);
                float w2 = fmaxf(rbx - ltx, 0.f), hh = fmaxf(rby - lty, 0.f);
                float inter = w2 * hh;
                float areaj = (jx2 - jx1) * (jy2 - jy1);
                float iou = inter / fmaxf(areai + areaj - inter, 1e-9f);
                if (iou > NMS_T) mask |= (1u << b);
            }
        }
        adj[idx] = mask;
    }
    __syncthreads();
    if (tid == 0) {
        unsigned supp[4];
#pragma unroll
        for (int w = 0; w < 4; w++) {
            int lo = w * 32;
            if (nv >= lo + 32) supp[w] = 0u;
            else if (nv <= lo) supp[w] = 0xFFFFFFFFu;
            else supp[w] = ~((1u << (nv - lo)) - 1u);
        }
        int kc = 0;
        for (int i = 0; i < KK; i++) {
            if (!((supp[i >> 5] >> (i & 31)) & 1u)) {
                g_keptK[c * KK + kc++] = i;
                supp[0] |= adj[i * 4 + 0]; supp[1] |= adj[i * 4 + 1];
                supp[2] |= adj[i * 4 + 2]; supp[3] |= adj[i * 4 + 3];
            }
        }
        g_kc[c] = kc;
    }
    __syncthreads();

    // ================= barrier 1: all classes done =================
    if (tid == 0) {
        __threadfence();
        atomicAdd(&g_bar1, 1);
    }

    // ================= Phase B: global top-D select (block 0) =================
    if (c == 0) {
        if (tid == 0) {
            while (atomicAdd(&g_bar1, 0) < NCLS) __nanosleep(64);
            __threadfence();
        }
        __syncthreads();
        for (int i = tid; i < SBINS; i += 512) sHist[i] = 0;
        if (tid < NCLS) sPref[tid + 1] = g_kc[tid];
        if (tid == 0) { sPref[0] = 0; sCnt = 0; }
        __syncthreads();
        for (int off = 1; off <= NCLS; off <<= 1) {   // Hillis-Steele scan
            int v = 0;
            if (tid <= NCLS && tid >= off) v = sPref[tid - off];
            __syncthreads();
            if (tid <= NCLS && tid >= off) sPref[tid] += v;
            __syncthreads();
        }
        int tot = sPref[NCLS];
        for (int g = tid; g < tot; g += 512) {
            int lo = 0, hi = NCLS;
            while (hi - lo > 1) { int mid = (lo + hi) >> 1; if (sPref[mid] <= g) lo = mid; else hi = mid; }
            int cc2 = lo, j = g - sPref[cc2];
            int k = g_keptK[cc2 * KK + j];
            unsigned v = __float_as_uint(g_vals[cc2 * KK + k]);
            int b = (int)(v >> 16) - SBASE;
            b = b < 0 ? 0 : (b > SBINS - 1 ? SBINS - 1 : b);
            atomicAdd(&sHist[b], 1);
        }
        __syncthreads();
        int r = tot < DD ? tot : DD;
        if (tid == 0) {
            int cum = 0, b = 0;
            for (int i = SBINS - 1; i >= 0; --i) { cum += sHist[i]; if (cum >= r) { b = i; break; } }
            sB = (r > 0) ? b : SBINS;
            sNum = r;
        }
        __syncthreads();
        int bstar = sB;
        for (int g = tid; g < tot; g += 512) {
            int lo = 0, hi = NCLS;
            while (hi - lo > 1) { int mid = (lo + hi) >> 1; if (sPref[mid] <= g) lo = mid; else hi = mid; }
            int cc2 = lo, j = g - sPref[cc2];
            int k = g_keptK[cc2 * KK + j];
            int ci = cc2 * KK + k;
            unsigned v = __float_as_uint(g_vals[ci]);
            int b = (int)(v >> 16) - SBASE;
            b = b < 0 ? 0 : (b > SBINS - 1 ? SBINS - 1 : b);
            if (b >= bstar) {
                int pos = atomicAdd(&sCnt, 1);
                if (pos < 1024)
                    sKeys[pos] = ((unsigned long long)v << 32) |
                                 (unsigned long long)(0xFFFFFFFFu - (unsigned)ci);
            }
        }
        __syncthreads();
        int cnt = sCnt; if (cnt > 1024) cnt = 1024;
        int np2 = 2; while (np2 < cnt) np2 <<= 1;
        for (int i = tid; i < np2; i += 512) if (i >= cnt) sKeys[i] = 0ull;
        __syncthreads();
        for (int size = 2; size <= np2; size <<= 1) {
            for (int stride = size >> 1; stride > 0; stride >>= 1) {
                for (int t = tid; t < (np2 >> 1); t += 512) {
                    int i = ((t & ~(stride - 1)) << 1) | (t & (stride - 1));
                    int j = i + stride;
                    bool dsc = ((i & size) == 0);
                    unsigned long long x = sKeys[i], y = sKeys[j];
                    if (dsc == (x < y)) { sKeys[i] = y; sKeys[j] = x; }
                }
                __syncthreads();
            }
        }
        int num = sNum;
        for (int t = tid; t < DD; t += 512) {
            if (t < num) {
                unsigned long long key = sKeys[t];
                int ci = (int)(0xFFFFFFFFu - (unsigned)key);
                int cc2 = ci / KK;
                g_selA[t] = g_anchor[ci];
                out[t * 4 + 0] = g_boxes[ci * 4 + 1];
                out[t * 4 + 1] = g_boxes[ci * 4 + 0];
                out[t * 4 + 2] = g_boxes[ci * 4 + 3];
                out[t * 4 + 3] = g_boxes[ci * 4 + 2];
                out[DD * 4 + t] = __uint_as_float((unsigned)(key >> 32));
                out[DD * 5 + t] = (float)(cc2 + 1);
            } else {
                g_selA[t] = -1;
                out[t * 4 + 0] = 0.f; out[t * 4 + 1] = 0.f;
                out[t * 4 + 2] = 0.f; out[t * 4 + 3] = 0.f;
                out[DD * 4 + t] = 0.f;
                out[DD * 5 + t] = 0.f;
            }
        }
        __syncthreads();
        if (tid == 0) { __threadfence(); atomicExch(&g_bar2, 1); }
    }

    // ================= barrier 2: selection published =================
    if (tid == 0) {
        while (atomicAdd(&g_bar2, 0) == 0) __nanosleep(64);
        __threadfence();
    }
    __syncthreads();

    // ================= Phase C: logit gather (90*512 threads) =================
    int gt = c * 512 + tid;
    for (int idx = gt; idx < DD * CC; idx += NCLS * 512) {
        int t = idx / CC, j = idx - t * CC;
        int a = g_selA[t];
        out[DD * 6 + idx] = (a >= 0) ? logits[(size_t)a * CC + j] : 0.f;
    }
    // reset per-launch state for next replay
    if (gt < NCLS) g_cnt[gt] = 0;
}

extern "C" void kernel_launch(void* const* d_in, const int* in_sizes, int n_in,
                              void* d_out, int out_size) {
    const float* logits = (const float*)d_in[0];
    const float* breg = (const float*)d_in[1];
    const float* anchors = (const float*)d_in[2];
    float* out = (float*)d_out;

    k_stats<<<592, 256>>>(logits);
    k_tail<<<NCLS, 512>>>(breg, anchors, out, logits);
}